// round 8
// baseline (speedup 1.0000x reference)
#include <cuda_runtime.h>
#include <math.h>

#define Bn 1024
#define Sn 100
#define En 128
#define Hn 128

// ---------------- scratch (device globals; no allocations allowed) ----------
__device__ float d_eg[(size_t)Bn * Sn * Hn];   // raw e_g  [b][s][h]
__device__ float d_tg[(size_t)Bn * Sn * Hn];   // tanh(e_g)
__device__ float d_tp[(size_t)Bn * Sn * Hn];   // tanh(e_p)
__device__ float d_hA[Bn * Hn];
__device__ float d_hB[Bn * Hn];
__device__ float d_c[Bn * Hn];
__device__ float d_x[Bn * En];
__device__ float d_tq[Bn * Hn];                // tanh(q) (glimpse, then pointer)
__device__ float d_w[Bn * Sn];                 // glimpse softmax weights
__device__ unsigned char d_mask[Bn * Sn];

#define NEGINF __int_as_float(0xff800000)

__device__ __forceinline__ float sigf(float x) { return 1.0f / (1.0f + expf(-x)); }

__device__ __forceinline__ float warp_sum(float v) {
#pragma unroll
    for (int o = 16; o > 0; o >>= 1) v += __shfl_xor_sync(0xffffffffu, v, o);
    return v;
}
__device__ __forceinline__ float warp_max(float v) {
#pragma unroll
    for (int o = 16; o > 0; o >>= 1) v = fmaxf(v, __shfl_xor_sync(0xffffffffu, v, o));
    return v;
}

// ---------------- init: copy states, zero mask ------------------------------
__global__ void k_init(const float* __restrict__ h0, const float* __restrict__ c0,
                       const float* __restrict__ x0) {
    int i = blockIdx.x * blockDim.x + threadIdx.x;
    if (i < Bn * Hn) { d_hA[i] = h0[i]; d_c[i] = c0[i]; }
    if (i < Bn * En) { d_x[i] = x0[i]; }
    if (i < Bn * Sn) { d_mask[i] = 0; }
}

// ---------------- precompute e_g, tanh(e_g), tanh(e_p) ----------------------
// block: 128 o x 128 b tile for one s; grid (B/128, S, 2). z=0 -> g, z=1 -> p.
__global__ void k_pre(const float* __restrict__ ctx,
                      const float* __restrict__ Wg, const float* __restrict__ bg,
                      const float* __restrict__ Wp, const float* __restrict__ bp) {
    extern __shared__ float sm[];
    float* Wsm = sm;             // [k][o] pitch 129
    float* Csm = sm + 128 * 129; // [k][b] pitch 128
    int b0 = blockIdx.x * 128;
    int s  = blockIdx.y;
    int z  = blockIdx.z;
    const float* W    = z ? Wp : Wg;
    const float* bias = z ? bp : bg;
    int tid = threadIdx.x;

    for (int idx = tid; idx < 128 * 128; idx += 256) {
        int o = idx >> 7, k = idx & 127;
        Wsm[k * 129 + o] = W[idx];
    }
    const float* cbase = ctx + (size_t)s * Hn * Bn + b0;
    for (int idx = tid; idx < 128 * 128; idx += 256) {
        int h = idx >> 7, bb = idx & 127;
        Csm[h * 128 + bb] = cbase[(size_t)h * Bn + bb];
    }
    __syncthreads();

    int tx = tid & 31, ty = tid >> 5;      // o = tx + 32i, b = ty*16 + j
    float acc[4][16];
#pragma unroll
    for (int i = 0; i < 4; i++)
#pragma unroll
        for (int j = 0; j < 16; j++) acc[i][j] = 0.0f;

    for (int k = 0; k < 128; k++) {
        float wv[4];
#pragma unroll
        for (int i = 0; i < 4; i++) wv[i] = Wsm[k * 129 + tx + 32 * i];
#pragma unroll
        for (int j = 0; j < 16; j++) {
            float cv = Csm[k * 128 + ty * 16 + j];
#pragma unroll
            for (int i = 0; i < 4; i++) acc[i][j] = fmaf(wv[i], cv, acc[i][j]);
        }
    }

#pragma unroll
    for (int j = 0; j < 16; j++) {
        int b = b0 + ty * 16 + j;
#pragma unroll
        for (int i = 0; i < 4; i++) {
            int o = tx + 32 * i;
            float val = acc[i][j] + bias[o];
            size_t off = ((size_t)b * Sn + s) * Hn + o;
            float tv = tanhf(val);
            if (z == 0) { d_eg[off] = val; d_tg[off] = tv; }
            else        { d_tp[off] = tv; }
        }
    }
}

// ---------------- LSTM gates GEMM + cell update ------------------------------
// block: 32 b x (32 units x 4 gates); grid (32, 4). t parity selects h ping-pong.
__global__ void k_gates(const float* __restrict__ Wi, const float* __restrict__ bi,
                        const float* __restrict__ Wh, const float* __restrict__ bh,
                        int t) {
    extern __shared__ float sm[];
    float* Wsm = sm;             // [k][n] pitch 129, k in [0,256)
    float* Asm = sm + 256 * 129; // [b][k] pitch 257
    const float* hin = (t & 1) ? d_hB : d_hA;
    float* hout      = (t & 1) ? d_hA : d_hB;

    int b0 = blockIdx.x * 32;
    int uc = blockIdx.y;
    int tid = threadIdx.x;

    for (int idx = tid; idx < 128 * 128; idx += 256) {
        int n = idx >> 7, k = idx & 127;
        int r = (n >> 5) * 128 + uc * 32 + (n & 31);
        Wsm[k * 129 + n]         = Wi[r * 128 + k];
        Wsm[(128 + k) * 129 + n] = Wh[r * 128 + k];
    }
    for (int idx = tid; idx < 32 * 128; idx += 256) {
        int b = idx >> 7, k = idx & 127;
        Asm[b * 257 + k]       = d_x[(b0 + b) * 128 + k];
        Asm[b * 257 + 128 + k] = hin[(b0 + b) * 128 + k];
    }
    __syncthreads();

    int ul = tid & 31, bg = tid >> 5;  // unit lane, batch group (4 b each)
    float acc[4][4];
#pragma unroll
    for (int g = 0; g < 4; g++)
#pragma unroll
        for (int bb = 0; bb < 4; bb++) acc[g][bb] = 0.0f;

    for (int k = 0; k < 256; k++) {
        float wv[4];
#pragma unroll
        for (int g = 0; g < 4; g++) wv[g] = Wsm[k * 129 + g * 32 + ul];
#pragma unroll
        for (int bb = 0; bb < 4; bb++) {
            float av = Asm[(bg * 4 + bb) * 257 + k];
#pragma unroll
            for (int g = 0; g < 4; g++) acc[g][bb] = fmaf(wv[g], av, acc[g][bb]);
        }
    }

    int unit = uc * 32 + ul;
    float bsum[4];
#pragma unroll
    for (int g = 0; g < 4; g++) bsum[g] = bi[g * 128 + unit] + bh[g * 128 + unit];

#pragma unroll
    for (int bb = 0; bb < 4; bb++) {
        int b = b0 + bg * 4 + bb;
        float iv = acc[0][bb] + bsum[0];
        float fv = acc[1][bb] + bsum[1];
        float gv = acc[2][bb] + bsum[2];
        float ov = acc[3][bb] + bsum[3];
        float c  = d_c[b * 128 + unit];
        float cy = sigf(fv) * c + sigf(iv) * tanhf(gv);
        float hy = sigf(ov) * tanhf(cy);
        d_c[b * 128 + unit]  = cy;
        hout[b * 128 + unit] = hy;
    }
}

// ---------------- q = hy @ gWq^T + gbq ; store tanh(q) -----------------------
__global__ void k_q(const float* __restrict__ W, const float* __restrict__ bq, int t) {
    extern __shared__ float sm[];
    float* Wsm = sm;             // [k][o] pitch 129
    float* Asm = sm + 128 * 129; // [b][k] pitch 129
    const float* hsrc = (t & 1) ? d_hA : d_hB;  // output of this step's k_gates

    int b0 = blockIdx.x * 16;
    int tid = threadIdx.x;

    for (int idx = tid; idx < 128 * 128; idx += 256) {
        int o = idx >> 7, k = idx & 127;
        Wsm[k * 129 + o] = W[idx];
    }
    for (int idx = tid; idx < 16 * 128; idx += 256) {
        int b = idx >> 7, k = idx & 127;
        Asm[b * 129 + k] = hsrc[(b0 + b) * 128 + k];
    }
    __syncthreads();

    int l = tid & 31, by = tid >> 5;   // o = l + 32i, b = by*2 + bb
    float acc[4][2];
#pragma unroll
    for (int i = 0; i < 4; i++) { acc[i][0] = 0.0f; acc[i][1] = 0.0f; }

    for (int k = 0; k < 128; k++) {
        float wv[4];
#pragma unroll
        for (int i = 0; i < 4; i++) wv[i] = Wsm[k * 129 + l + 32 * i];
#pragma unroll
        for (int bb = 0; bb < 2; bb++) {
            float av = Asm[(by * 2 + bb) * 129 + k];
#pragma unroll
            for (int i = 0; i < 4; i++) acc[i][bb] = fmaf(wv[i], av, acc[i][bb]);
        }
    }
#pragma unroll
    for (int bb = 0; bb < 2; bb++)
#pragma unroll
        for (int i = 0; i < 4; i++) {
            int o = l + 32 * i;
            int b = b0 + by * 2 + bb;
            d_tq[b * 128 + o] = tanhf(acc[i][bb] + bq[o]);
        }
}

// ---------------- glimpse attention: u, mask, softmax -> w -------------------
__global__ void k_att_g(const float* __restrict__ gv) {
    int b = blockIdx.x;
    __shared__ __align__(16) float tqs[128];
    __shared__ __align__(16) float vs[128];
    __shared__ float us[104];
    __shared__ unsigned char ms[100];
    int tid = threadIdx.x;
    if (tid < 128) { tqs[tid] = d_tq[b * 128 + tid]; vs[tid] = gv[tid]; }
    if (tid < 100) ms[tid] = d_mask[b * 100 + tid];
    __syncthreads();

    int w = tid >> 5, l = tid & 31;
    float4 tq = ((const float4*)tqs)[l];
    float4 vv = ((const float4*)vs)[l];
    for (int s = w; s < Sn; s += 8) {
        float4 te = *(const float4*)(&d_tg[((size_t)b * Sn + s) * Hn + 4 * l]);
        float a;
        a = vv.x * __fdividef(tq.x + te.x, fmaf(tq.x, te.x, 1.0f));
        a = fmaf(vv.y, __fdividef(tq.y + te.y, fmaf(tq.y, te.y, 1.0f)), a);
        a = fmaf(vv.z, __fdividef(tq.z + te.z, fmaf(tq.z, te.z, 1.0f)), a);
        a = fmaf(vv.w, __fdividef(tq.w + te.w, fmaf(tq.w, te.w, 1.0f)), a);
        a = warp_sum(a);
        if (l == 0) us[s] = ms[s] ? NEGINF : a;
    }
    __syncthreads();

    if (w == 0) {
        float v0[4];
#pragma unroll
        for (int k = 0; k < 4; k++) {
            int s = l + 32 * k;
            v0[k] = (s < Sn) ? us[s] : NEGINF;
        }
        float m = fmaxf(fmaxf(v0[0], v0[1]), fmaxf(v0[2], v0[3]));
        m = warp_max(m);
        float e[4], loc = 0.0f;
#pragma unroll
        for (int k = 0; k < 4; k++) {
            int s = l + 32 * k;
            e[k] = (s < Sn) ? expf(v0[k] - m) : 0.0f;
            loc += e[k];
        }
        float tot = warp_sum(loc);
        float inv = 1.0f / tot;
#pragma unroll
        for (int k = 0; k < 4; k++) {
            int s = l + 32 * k;
            if (s < Sn) d_w[b * Sn + s] = e[k] * inv;
        }
    }
}

// ---------------- gl = sum_s w*e_g ; q_p = gl@pWq^T + pbq ; store tanh -------
__global__ void k_glqp(const float* __restrict__ pWq, const float* __restrict__ pbq) {
    extern __shared__ float sm[];
    float* Wsm = sm;                  // [k][o] pitch 129 (16512 floats)
    float* gls = sm + 128 * 129;      // [bb][h] 8*128 floats (16B aligned)
    float* wsm = gls + 8 * 128;       // 800 floats
    int b0 = blockIdx.x * 8;
    int tid = threadIdx.x;

    for (int idx = tid; idx < 128 * 128; idx += 256) {
        int o = idx >> 7, k = idx & 127;
        Wsm[k * 129 + o] = pWq[idx];
    }
    for (int idx = tid; idx < 8 * Sn; idx += 256) wsm[idx] = d_w[b0 * Sn + idx];
    __syncthreads();

    int bb = tid >> 5, l = tid & 31;
    int b = b0 + bb;

    // phase A: gl[bb][4l..4l+3]
    float4 acc = make_float4(0.f, 0.f, 0.f, 0.f);
    const float* wrow = wsm + bb * Sn;
    const float* ebase = d_eg + ((size_t)b * Sn) * Hn + 4 * l;
#pragma unroll 4
    for (int s = 0; s < Sn; s++) {
        float ws = wrow[s];
        float4 e = *(const float4*)(ebase + (size_t)s * Hn);
        acc.x = fmaf(ws, e.x, acc.x);
        acc.y = fmaf(ws, e.y, acc.y);
        acc.z = fmaf(ws, e.z, acc.z);
        acc.w = fmaf(ws, e.w, acc.w);
    }
    ((float4*)gls)[bb * 32 + l] = acc;
    __syncthreads();

    // phase B: q_p[bb][o] then tanh
    float a[4] = {0.f, 0.f, 0.f, 0.f};
    const float* g = gls + bb * 128;
    for (int k = 0; k < 128; k++) {
        float gk = g[k];
#pragma unroll
        for (int i = 0; i < 4; i++) a[i] = fmaf(Wsm[k * 129 + l + 32 * i], gk, a[i]);
    }
#pragma unroll
    for (int i = 0; i < 4; i++) {
        int o = l + 32 * i;
        d_tq[b * 128 + o] = tanhf(a[i] + pbq[o]);
    }
}

// ---------------- pointer attention: logits, probs, argmax, mask, gather ----
__global__ void k_att_p(const float* __restrict__ pv, const float* __restrict__ emb,
                        float* __restrict__ out, int t) {
    int b = blockIdx.x;
    __shared__ __align__(16) float tqs[128];
    __shared__ __align__(16) float vs[128];
    __shared__ float us[104];
    __shared__ unsigned char ms[100];
    __shared__ int sidx;
    int tid = threadIdx.x;
    if (tid < 128) { tqs[tid] = d_tq[b * 128 + tid]; vs[tid] = pv[tid]; }
    if (tid < 100) ms[tid] = d_mask[b * 100 + tid];
    __syncthreads();

    int w = tid >> 5, l = tid & 31;
    float4 tq = ((const float4*)tqs)[l];
    float4 vv = ((const float4*)vs)[l];
    for (int s = w; s < Sn; s += 8) {
        float4 te = *(const float4*)(&d_tp[((size_t)b * Sn + s) * Hn + 4 * l]);
        float a;
        a = vv.x * __fdividef(tq.x + te.x, fmaf(tq.x, te.x, 1.0f));
        a = fmaf(vv.y, __fdividef(tq.y + te.y, fmaf(tq.y, te.y, 1.0f)), a);
        a = fmaf(vv.z, __fdividef(tq.z + te.z, fmaf(tq.z, te.z, 1.0f)), a);
        a = fmaf(vv.w, __fdividef(tq.w + te.w, fmaf(tq.w, te.w, 1.0f)), a);
        a = warp_sum(a);
        if (l == 0) us[s] = ms[s] ? NEGINF : (10.0f * tanhf(a));
    }
    __syncthreads();

    if (w == 0) {
        float v0[4];
#pragma unroll
        for (int k = 0; k < 4; k++) {
            int s = l + 32 * k;
            v0[k] = (s < Sn) ? us[s] : NEGINF;
        }
        float m = fmaxf(fmaxf(v0[0], v0[1]), fmaxf(v0[2], v0[3]));
        m = warp_max(m);
        float e[4], loc = 0.0f;
#pragma unroll
        for (int k = 0; k < 4; k++) {
            int s = l + 32 * k;
            e[k] = (s < Sn) ? expf(v0[k] - m) : 0.0f;
            loc += e[k];
        }
        float tot = warp_sum(loc);
        float inv = 1.0f / tot;
        size_t pbase = ((size_t)t * Bn + b) * Sn;
#pragma unroll
        for (int k = 0; k < 4; k++) {
            int s = l + 32 * k;
            if (s < Sn) out[pbase + s] = e[k] * inv;
        }
        // argmax of logits (== argmax of probs), first index wins on tie
        float bv = NEGINF; int bidx = 0;
#pragma unroll
        for (int k = 0; k < 4; k++) {
            int s = l + 32 * k;
            if (s < Sn && v0[k] > bv) { bv = v0[k]; bidx = s; }
        }
#pragma unroll
        for (int o = 16; o > 0; o >>= 1) {
            float ov = __shfl_xor_sync(0xffffffffu, bv, o);
            int   oi = __shfl_xor_sync(0xffffffffu, bidx, o);
            if (ov > bv || (ov == bv && oi < bidx)) { bv = ov; bidx = oi; }
        }
        if (l == 0) {
            out[(size_t)Sn * Bn * Sn + (size_t)t * Bn + b] = (float)bidx;
            d_mask[b * Sn + bidx] = 1;
            sidx = bidx;
        }
    }
    __syncthreads();
    if (tid < En) d_x[b * En + tid] = emb[((size_t)sidx * Bn + b) * En + tid];
}

// ---------------- final: write hx, cx ---------------------------------------
__global__ void k_fin(float* __restrict__ out) {
    int i = blockIdx.x * blockDim.x + threadIdx.x;
    size_t base = (size_t)Sn * Bn * Sn + (size_t)Sn * Bn;
    if (i < Bn * Hn) {
        out[base + i] = d_hA[i];               // t=99 (odd) wrote d_hA
        out[base + Bn * Hn + i] = d_c[i];
    }
}

// ---------------- host launch ------------------------------------------------
extern "C" void kernel_launch(void* const* d_in, const int* in_sizes, int n_in,
                              void* d_out, int out_size) {
    const float* dec = (const float*)d_in[0];
    const float* emb = (const float*)d_in[1];
    const float* h0  = (const float*)d_in[2];
    const float* c0  = (const float*)d_in[3];
    const float* ctx = (const float*)d_in[4];
    const float* Wi  = (const float*)d_in[5];
    const float* bi  = (const float*)d_in[6];
    const float* Wh  = (const float*)d_in[7];
    const float* bh  = (const float*)d_in[8];
    const float* gWq = (const float*)d_in[9];
    const float* gbq = (const float*)d_in[10];
    const float* gWr = (const float*)d_in[11];
    const float* gbr = (const float*)d_in[12];
    const float* gv  = (const float*)d_in[13];
    const float* pWq = (const float*)d_in[14];
    const float* pbq = (const float*)d_in[15];
    const float* pWr = (const float*)d_in[16];
    const float* pbr = (const float*)d_in[17];
    const float* pv  = (const float*)d_in[18];
    float* out = (float*)d_out;

    const int SM_PRE   = (128 * 129 + 128 * 128) * 4;           // 131584
    const int SM_GATES = (256 * 129 + 32 * 257) * 4;            // 164992
    const int SM_Q     = (128 * 129 + 16 * 129) * 4;            // 74304
    const int SM_GL    = (128 * 129 + 8 * 128 + 8 * Sn) * 4;    // 73344

    cudaFuncSetAttribute(k_pre,   cudaFuncAttributeMaxDynamicSharedMemorySize, SM_PRE);
    cudaFuncSetAttribute(k_gates, cudaFuncAttributeMaxDynamicSharedMemorySize, SM_GATES);
    cudaFuncSetAttribute(k_q,     cudaFuncAttributeMaxDynamicSharedMemorySize, SM_Q);
    cudaFuncSetAttribute(k_glqp,  cudaFuncAttributeMaxDynamicSharedMemorySize, SM_GL);

    k_init<<<512, 256>>>(h0, c0, dec);
    k_pre<<<dim3(Bn / 128, Sn, 2), 256, SM_PRE>>>(ctx, gWr, gbr, pWr, pbr);

    for (int t = 0; t < Sn; t++) {
        k_gates<<<dim3(32, 4), 256, SM_GATES>>>(Wi, bi, Wh, bh, t);
        k_q<<<Bn / 16, 256, SM_Q>>>(gWq, gbq, t);
        k_att_g<<<Bn, 256>>>(gv);
        k_glqp<<<Bn / 8, 256, SM_GL>>>(pWq, pbq);
        k_att_p<<<Bn, 256>>>(pv, emb, out, t);
    }
    k_fin<<<512, 256>>>(out);
}

// round 9
// speedup vs baseline: 1.0065x; 1.0065x over previous
#include <cuda_runtime.h>
#include <math.h>

#define Bn 1024
#define Sn 100
#define En 128
#define Hn 128

// ---------------- scratch (device globals; no allocations allowed) ----------
__device__ float d_eg[(size_t)Bn * Sn * Hn];   // raw e_g  [b][s][h]
__device__ float d_tg[(size_t)Bn * Sn * Hn];   // tanh(e_g)
__device__ float d_tp[(size_t)Bn * Sn * Hn];   // tanh(e_p)
__device__ float d_hA[Bn * Hn];
__device__ float d_hB[Bn * Hn];
__device__ float d_c[Bn * Hn];
__device__ float d_x[Bn * En];
__device__ float d_tq[Bn * Hn];                // tanh(q) (glimpse, then pointer)
__device__ float d_w[Bn * Sn];                 // glimpse softmax weights
__device__ unsigned char d_mask[Bn * Sn];

#define NEGINF __int_as_float(0xff800000)

__device__ __forceinline__ float sigf(float x) { return 1.0f / (1.0f + expf(-x)); }

__device__ __forceinline__ float warp_sum(float v) {
#pragma unroll
    for (int o = 16; o > 0; o >>= 1) v += __shfl_xor_sync(0xffffffffu, v, o);
    return v;
}
__device__ __forceinline__ float warp_max(float v) {
#pragma unroll
    for (int o = 16; o > 0; o >>= 1) v = fmaxf(v, __shfl_xor_sync(0xffffffffu, v, o));
    return v;
}

// ---------------- init: copy states, zero mask ------------------------------
__global__ void k_init(const float* __restrict__ h0, const float* __restrict__ c0,
                       const float* __restrict__ x0) {
    int i = blockIdx.x * blockDim.x + threadIdx.x;
    if (i < Bn * Hn) { d_hA[i] = h0[i]; d_c[i] = c0[i]; }
    if (i < Bn * En) { d_x[i] = x0[i]; }
    if (i < Bn * Sn) { d_mask[i] = 0; }
}

// ---------------- precompute e_g, tanh(e_g), tanh(e_p) ----------------------
// block: 128 o x 128 b tile for one s; grid (B/128, S, 2). z=0 -> g, z=1 -> p.
__global__ void k_pre(const float* __restrict__ ctx,
                      const float* __restrict__ Wg, const float* __restrict__ bg,
                      const float* __restrict__ Wp, const float* __restrict__ bp) {
    extern __shared__ float sm[];
    float* Wsm = sm;             // [k][o] pitch 129
    float* Csm = sm + 128 * 129; // [k][b] pitch 128
    int b0 = blockIdx.x * 128;
    int s  = blockIdx.y;
    int z  = blockIdx.z;
    const float* W    = z ? Wp : Wg;
    const float* bias = z ? bp : bg;
    int tid = threadIdx.x;

    for (int idx = tid; idx < 128 * 128; idx += 256) {
        int o = idx >> 7, k = idx & 127;
        Wsm[k * 129 + o] = W[idx];
    }
    const float* cbase = ctx + (size_t)s * Hn * Bn + b0;
    for (int idx = tid; idx < 128 * 128; idx += 256) {
        int h = idx >> 7, bb = idx & 127;
        Csm[h * 128 + bb] = cbase[(size_t)h * Bn + bb];
    }
    __syncthreads();

    int tx = tid & 31, ty = tid >> 5;      // o = tx + 32i, b = ty*16 + j
    float acc[4][16];
#pragma unroll
    for (int i = 0; i < 4; i++)
#pragma unroll
        for (int j = 0; j < 16; j++) acc[i][j] = 0.0f;

    for (int k = 0; k < 128; k++) {
        float wv[4];
#pragma unroll
        for (int i = 0; i < 4; i++) wv[i] = Wsm[k * 129 + tx + 32 * i];
#pragma unroll
        for (int j = 0; j < 16; j++) {
            float cv = Csm[k * 128 + ty * 16 + j];
#pragma unroll
            for (int i = 0; i < 4; i++) acc[i][j] = fmaf(wv[i], cv, acc[i][j]);
        }
    }

#pragma unroll
    for (int j = 0; j < 16; j++) {
        int b = b0 + ty * 16 + j;
#pragma unroll
        for (int i = 0; i < 4; i++) {
            int o = tx + 32 * i;
            float val = acc[i][j] + bias[o];
            size_t off = ((size_t)b * Sn + s) * Hn + o;
            float tv = tanhf(val);
            if (z == 0) { d_eg[off] = val; d_tg[off] = tv; }
            else        { d_tp[off] = tv; }
        }
    }
}

// ---------------- LSTM gates GEMM + cell update ------------------------------
// block: 32 b x (32 units x 4 gates); grid (32, 4). t parity selects h ping-pong.
__global__ void k_gates(const float* __restrict__ Wi, const float* __restrict__ bi,
                        const float* __restrict__ Wh, const float* __restrict__ bh,
                        int t) {
    extern __shared__ float sm[];
    float* Wsm = sm;             // [k][n] pitch 129, k in [0,256)
    float* Asm = sm + 256 * 129; // [b][k] pitch 257
    const float* hin = (t & 1) ? d_hB : d_hA;
    float* hout      = (t & 1) ? d_hA : d_hB;

    int b0 = blockIdx.x * 32;
    int uc = blockIdx.y;
    int tid = threadIdx.x;

    for (int idx = tid; idx < 128 * 128; idx += 256) {
        int n = idx >> 7, k = idx & 127;
        int r = (n >> 5) * 128 + uc * 32 + (n & 31);
        Wsm[k * 129 + n]         = Wi[r * 128 + k];
        Wsm[(128 + k) * 129 + n] = Wh[r * 128 + k];
    }
    for (int idx = tid; idx < 32 * 128; idx += 256) {
        int b = idx >> 7, k = idx & 127;
        Asm[b * 257 + k]       = d_x[(b0 + b) * 128 + k];
        Asm[b * 257 + 128 + k] = hin[(b0 + b) * 128 + k];
    }
    __syncthreads();

    int ul = tid & 31, bg = tid >> 5;  // unit lane, batch group (4 b each)
    float acc[4][4];
#pragma unroll
    for (int g = 0; g < 4; g++)
#pragma unroll
        for (int bb = 0; bb < 4; bb++) acc[g][bb] = 0.0f;

    for (int k = 0; k < 256; k++) {
        float wv[4];
#pragma unroll
        for (int g = 0; g < 4; g++) wv[g] = Wsm[k * 129 + g * 32 + ul];
#pragma unroll
        for (int bb = 0; bb < 4; bb++) {
            float av = Asm[(bg * 4 + bb) * 257 + k];
#pragma unroll
            for (int g = 0; g < 4; g++) acc[g][bb] = fmaf(wv[g], av, acc[g][bb]);
        }
    }

    int unit = uc * 32 + ul;
    float bsum[4];
#pragma unroll
    for (int g = 0; g < 4; g++) bsum[g] = bi[g * 128 + unit] + bh[g * 128 + unit];

#pragma unroll
    for (int bb = 0; bb < 4; bb++) {
        int b = b0 + bg * 4 + bb;
        float iv = acc[0][bb] + bsum[0];
        float fv = acc[1][bb] + bsum[1];
        float gv = acc[2][bb] + bsum[2];
        float ov = acc[3][bb] + bsum[3];
        float c  = d_c[b * 128 + unit];
        float cy = sigf(fv) * c + sigf(iv) * tanhf(gv);
        float hy = sigf(ov) * tanhf(cy);
        d_c[b * 128 + unit]  = cy;
        hout[b * 128 + unit] = hy;
    }
}

// ---------------- q = hy @ gWq^T + gbq ; store tanh(q) -----------------------
__global__ void k_q(const float* __restrict__ W, const float* __restrict__ bq, int t) {
    extern __shared__ float sm[];
    float* Wsm = sm;             // [k][o] pitch 129
    float* Asm = sm + 128 * 129; // [b][k] pitch 129
    const float* hsrc = (t & 1) ? d_hA : d_hB;  // output of this step's k_gates

    int b0 = blockIdx.x * 16;
    int tid = threadIdx.x;

    for (int idx = tid; idx < 128 * 128; idx += 256) {
        int o = idx >> 7, k = idx & 127;
        Wsm[k * 129 + o] = W[idx];
    }
    for (int idx = tid; idx < 16 * 128; idx += 256) {
        int b = idx >> 7, k = idx & 127;
        Asm[b * 129 + k] = hsrc[(b0 + b) * 128 + k];
    }
    __syncthreads();

    int l = tid & 31, by = tid >> 5;   // o = l + 32i, b = by*2 + bb
    float acc[4][2];
#pragma unroll
    for (int i = 0; i < 4; i++) { acc[i][0] = 0.0f; acc[i][1] = 0.0f; }

    for (int k = 0; k < 128; k++) {
        float wv[4];
#pragma unroll
        for (int i = 0; i < 4; i++) wv[i] = Wsm[k * 129 + l + 32 * i];
#pragma unroll
        for (int bb = 0; bb < 2; bb++) {
            float av = Asm[(by * 2 + bb) * 129 + k];
#pragma unroll
            for (int i = 0; i < 4; i++) acc[i][bb] = fmaf(wv[i], av, acc[i][bb]);
        }
    }
#pragma unroll
    for (int bb = 0; bb < 2; bb++)
#pragma unroll
        for (int i = 0; i < 4; i++) {
            int o = l + 32 * i;
            int b = b0 + by * 2 + bb;
            d_tq[b * 128 + o] = tanhf(acc[i][bb] + bq[o]);
        }
}

// ---------------- glimpse attention: u, mask, softmax -> w -------------------
__global__ void k_att_g(const float* __restrict__ gv) {
    int b = blockIdx.x;
    __shared__ __align__(16) float tqs[128];
    __shared__ __align__(16) float vs[128];
    __shared__ float us[104];
    __shared__ unsigned char ms[100];
    int tid = threadIdx.x;
    if (tid < 128) { tqs[tid] = d_tq[b * 128 + tid]; vs[tid] = gv[tid]; }
    if (tid < 100) ms[tid] = d_mask[b * 100 + tid];
    __syncthreads();

    int w = tid >> 5, l = tid & 31;
    float4 tq = ((const float4*)tqs)[l];
    float4 vv = ((const float4*)vs)[l];
    for (int s = w; s < Sn; s += 8) {
        float4 te = *(const float4*)(&d_tg[((size_t)b * Sn + s) * Hn + 4 * l]);
        float a;
        a = vv.x * __fdividef(tq.x + te.x, fmaf(tq.x, te.x, 1.0f));
        a = fmaf(vv.y, __fdividef(tq.y + te.y, fmaf(tq.y, te.y, 1.0f)), a);
        a = fmaf(vv.z, __fdividef(tq.z + te.z, fmaf(tq.z, te.z, 1.0f)), a);
        a = fmaf(vv.w, __fdividef(tq.w + te.w, fmaf(tq.w, te.w, 1.0f)), a);
        a = warp_sum(a);
        if (l == 0) us[s] = ms[s] ? NEGINF : a;
    }
    __syncthreads();

    if (w == 0) {
        float v0[4];
#pragma unroll
        for (int k = 0; k < 4; k++) {
            int s = l + 32 * k;
            v0[k] = (s < Sn) ? us[s] : NEGINF;
        }
        float m = fmaxf(fmaxf(v0[0], v0[1]), fmaxf(v0[2], v0[3]));
        m = warp_max(m);
        float e[4], loc = 0.0f;
#pragma unroll
        for (int k = 0; k < 4; k++) {
            int s = l + 32 * k;
            e[k] = (s < Sn) ? expf(v0[k] - m) : 0.0f;
            loc += e[k];
        }
        float tot = warp_sum(loc);
        float inv = 1.0f / tot;
#pragma unroll
        for (int k = 0; k < 4; k++) {
            int s = l + 32 * k;
            if (s < Sn) d_w[b * Sn + s] = e[k] * inv;
        }
    }
}

// ---------------- gl = sum_s w*e_g ; q_p = gl@pWq^T + pbq ; store tanh -------
__global__ void k_glqp(const float* __restrict__ pWq, const float* __restrict__ pbq) {
    extern __shared__ float sm[];
    float* Wsm = sm;                  // [k][o] pitch 129 (16512 floats)
    float* gls = sm + 128 * 129;      // [bb][h] 8*128 floats (16B aligned)
    float* wsm = gls + 8 * 128;       // 800 floats
    int b0 = blockIdx.x * 8;
    int tid = threadIdx.x;

    for (int idx = tid; idx < 128 * 128; idx += 256) {
        int o = idx >> 7, k = idx & 127;
        Wsm[k * 129 + o] = pWq[idx];
    }
    for (int idx = tid; idx < 8 * Sn; idx += 256) wsm[idx] = d_w[b0 * Sn + idx];
    __syncthreads();

    int bb = tid >> 5, l = tid & 31;
    int b = b0 + bb;

    // phase A: gl[bb][4l..4l+3]
    float4 acc = make_float4(0.f, 0.f, 0.f, 0.f);
    const float* wrow = wsm + bb * Sn;
    const float* ebase = d_eg + ((size_t)b * Sn) * Hn + 4 * l;
#pragma unroll 4
    for (int s = 0; s < Sn; s++) {
        float ws = wrow[s];
        float4 e = *(const float4*)(ebase + (size_t)s * Hn);
        acc.x = fmaf(ws, e.x, acc.x);
        acc.y = fmaf(ws, e.y, acc.y);
        acc.z = fmaf(ws, e.z, acc.z);
        acc.w = fmaf(ws, e.w, acc.w);
    }
    ((float4*)gls)[bb * 32 + l] = acc;
    __syncthreads();

    // phase B: q_p[bb][o] then tanh
    float a[4] = {0.f, 0.f, 0.f, 0.f};
    const float* g = gls + bb * 128;
    for (int k = 0; k < 128; k++) {
        float gk = g[k];
#pragma unroll
        for (int i = 0; i < 4; i++) a[i] = fmaf(Wsm[k * 129 + l + 32 * i], gk, a[i]);
    }
#pragma unroll
    for (int i = 0; i < 4; i++) {
        int o = l + 32 * i;
        d_tq[b * 128 + o] = tanhf(a[i] + pbq[o]);
    }
}

// ---------------- pointer attention: logits, probs, argmax, mask, gather ----
__global__ void k_att_p(const float* __restrict__ pv, const float* __restrict__ emb,
                        float* __restrict__ out, int t) {
    int b = blockIdx.x;
    __shared__ __align__(16) float tqs[128];
    __shared__ __align__(16) float vs[128];
    __shared__ float us[104];
    __shared__ unsigned char ms[100];
    __shared__ int sidx;
    int tid = threadIdx.x;
    if (tid < 128) { tqs[tid] = d_tq[b * 128 + tid]; vs[tid] = pv[tid]; }
    if (tid < 100) ms[tid] = d_mask[b * 100 + tid];
    __syncthreads();

    int w = tid >> 5, l = tid & 31;
    float4 tq = ((const float4*)tqs)[l];
    float4 vv = ((const float4*)vs)[l];
    for (int s = w; s < Sn; s += 8) {
        float4 te = *(const float4*)(&d_tp[((size_t)b * Sn + s) * Hn + 4 * l]);
        float a;
        a = vv.x * __fdividef(tq.x + te.x, fmaf(tq.x, te.x, 1.0f));
        a = fmaf(vv.y, __fdividef(tq.y + te.y, fmaf(tq.y, te.y, 1.0f)), a);
        a = fmaf(vv.z, __fdividef(tq.z + te.z, fmaf(tq.z, te.z, 1.0f)), a);
        a = fmaf(vv.w, __fdividef(tq.w + te.w, fmaf(tq.w, te.w, 1.0f)), a);
        a = warp_sum(a);
        if (l == 0) us[s] = ms[s] ? NEGINF : (10.0f * tanhf(a));
    }
    __syncthreads();

    if (w == 0) {
        float v0[4];
#pragma unroll
        for (int k = 0; k < 4; k++) {
            int s = l + 32 * k;
            v0[k] = (s < Sn) ? us[s] : NEGINF;
        }
        float m = fmaxf(fmaxf(v0[0], v0[1]), fmaxf(v0[2], v0[3]));
        m = warp_max(m);
        float e[4], loc = 0.0f;
#pragma unroll
        for (int k = 0; k < 4; k++) {
            int s = l + 32 * k;
            e[k] = (s < Sn) ? expf(v0[k] - m) : 0.0f;
            loc += e[k];
        }
        float tot = warp_sum(loc);
        float inv = 1.0f / tot;
        size_t pbase = ((size_t)t * Bn + b) * Sn;
#pragma unroll
        for (int k = 0; k < 4; k++) {
            int s = l + 32 * k;
            if (s < Sn) out[pbase + s] = e[k] * inv;
        }
        // argmax of logits (== argmax of probs), first index wins on tie
        float bv = NEGINF; int bidx = 0;
#pragma unroll
        for (int k = 0; k < 4; k++) {
            int s = l + 32 * k;
            if (s < Sn && v0[k] > bv) { bv = v0[k]; bidx = s; }
        }
#pragma unroll
        for (int o = 16; o > 0; o >>= 1) {
            float ov = __shfl_xor_sync(0xffffffffu, bv, o);
            int   oi = __shfl_xor_sync(0xffffffffu, bidx, o);
            if (ov > bv || (ov == bv && oi < bidx)) { bv = ov; bidx = oi; }
        }
        if (l == 0) {
            out[(size_t)Sn * Bn * Sn + (size_t)t * Bn + b] = (float)bidx;
            d_mask[b * Sn + bidx] = 1;
            sidx = bidx;
        }
    }
    __syncthreads();
    if (tid < En) d_x[b * En + tid] = emb[((size_t)sidx * Bn + b) * En + tid];
}

// ---------------- final: write hx, cx ---------------------------------------
__global__ void k_fin(float* __restrict__ out) {
    int i = blockIdx.x * blockDim.x + threadIdx.x;
    size_t base = (size_t)Sn * Bn * Sn + (size_t)Sn * Bn;
    if (i < Bn * Hn) {
        out[base + i] = d_hA[i];               // t=99 (odd) wrote d_hA
        out[base + Bn * Hn + i] = d_c[i];
    }
}

// ---------------- host launch ------------------------------------------------
extern "C" void kernel_launch(void* const* d_in, const int* in_sizes, int n_in,
                              void* d_out, int out_size) {
    const float* dec = (const float*)d_in[0];
    const float* emb = (const float*)d_in[1];
    const float* h0  = (const float*)d_in[2];
    const float* c0  = (const float*)d_in[3];
    const float* ctx = (const float*)d_in[4];
    const float* Wi  = (const float*)d_in[5];
    const float* bi  = (const float*)d_in[6];
    const float* Wh  = (const float*)d_in[7];
    const float* bh  = (const float*)d_in[8];
    const float* gWq = (const float*)d_in[9];
    const float* gbq = (const float*)d_in[10];
    const float* gWr = (const float*)d_in[11];
    const float* gbr = (const float*)d_in[12];
    const float* gv  = (const float*)d_in[13];
    const float* pWq = (const float*)d_in[14];
    const float* pbq = (const float*)d_in[15];
    const float* pWr = (const float*)d_in[16];
    const float* pbr = (const float*)d_in[17];
    const float* pv  = (const float*)d_in[18];
    float* out = (float*)d_out;

    const int SM_PRE   = (128 * 129 + 128 * 128) * 4;           // 131584
    const int SM_GATES = (256 * 129 + 32 * 257) * 4;            // 164992
    const int SM_Q     = (128 * 129 + 16 * 129) * 4;            // 74304
    const int SM_GL    = (128 * 129 + 8 * 128 + 8 * Sn) * 4;    // 73344

    cudaFuncSetAttribute(k_pre,   cudaFuncAttributeMaxDynamicSharedMemorySize, SM_PRE);
    cudaFuncSetAttribute(k_gates, cudaFuncAttributeMaxDynamicSharedMemorySize, SM_GATES);
    cudaFuncSetAttribute(k_q,     cudaFuncAttributeMaxDynamicSharedMemorySize, SM_Q);
    cudaFuncSetAttribute(k_glqp,  cudaFuncAttributeMaxDynamicSharedMemorySize, SM_GL);

    k_init<<<512, 256>>>(h0, c0, dec);
    k_pre<<<dim3(Bn / 128, Sn, 2), 256, SM_PRE>>>(ctx, gWr, gbr, pWr, pbr);

    for (int t = 0; t < Sn; t++) {
        k_gates<<<dim3(32, 4), 256, SM_GATES>>>(Wi, bi, Wh, bh, t);
        k_q<<<Bn / 16, 256, SM_Q>>>(gWq, gbq, t);
        k_att_g<<<Bn, 256>>>(gv);
        k_glqp<<<Bn / 8, 256, SM_GL>>>(pWq, pbq);
        k_att_p<<<Bn, 256>>>(pv, emb, out, t);
    }
    k_fin<<<512, 256>>>(out);
}